// round 13
// baseline (speedup 1.0000x reference)
#include <cuda_runtime.h>

// FINAL: out[b,i,j,f] = x[b,i,f] * y[b,j,f]; d_out second half = 0.75 * first.
// One thread per (b, i, f4): 4 coalesced float4 loads (x[b,i], y[b,0..2]),
// 6 coalesced float4 stores grouped by output half. 128-thread blocks.
// Measured at the mixed 1:3 R/W DRAM wall: traffic = mandatory 1.17GB,
// ~83% of spec HBM bandwidth (matches chip ceiling for this mix).
// Rejected by measurement: ldcs/stcs, v8 256-bit ld/st, persistent grid,
// batch-2 unrolling, single-linear-stream stores, coarser/finer CTAs.

__global__ __launch_bounds__(128)
void tp_kernel(const float4* __restrict__ x,
               const float4* __restrict__ y,
               float4* __restrict__ out,
               unsigned total, unsigned halfi)
{
    unsigned idx = blockIdx.x * blockDim.x + threadIdx.x;
    if (idx >= total) return;

    unsigned f4 = idx & 31u;
    unsigned g  = idx >> 5;          // b*3 + i
    unsigned b  = g / 3u;
    unsigned i  = g - b * 3u;

    float4 xv = x[g * 32u + f4];

    float4 yv[3];
#pragma unroll
    for (int j = 0; j < 3; j++)
        yv[j] = y[(b * 3u + j) * 32u + f4];

    float4 p[3];
#pragma unroll
    for (int j = 0; j < 3; j++) {
        p[j].x = xv.x * yv[j].x;
        p[j].y = xv.y * yv[j].y;
        p[j].z = xv.z * yv[j].z;
        p[j].w = xv.w * yv[j].w;
    }

    unsigned obase = (b * 9u + i * 3u) * 32u + f4;

#pragma unroll
    for (int j = 0; j < 3; j++)
        out[obase + j * 32u] = p[j];

#pragma unroll
    for (int j = 0; j < 3; j++) {
        float4 q;
        q.x = 0.75f * p[j].x;
        q.y = 0.75f * p[j].y;
        q.z = 0.75f * p[j].z;
        q.w = 0.75f * p[j].w;
        out[halfi + obase + j * 32u] = q;
    }
}

extern "C" void kernel_launch(void* const* d_in, const int* in_sizes, int n_in,
                              void* d_out, int out_size)
{
    const float4* x = (const float4*)d_in[0];
    const float4* y = (const float4*)d_in[1];
    float4* out = (float4*)d_out;

    int B = in_sizes[0] / (3 * 128);          // 100000
    unsigned total = (unsigned)B * 3u * 32u;  // threads: (b, i, f4)
    unsigned halfi = (unsigned)B * 9u * 32u;  // float4 elems in first half
    int threads = 128;
    int blocks = (int)((total + threads - 1) / threads);
    tp_kernel<<<blocks, threads>>>(x, y, out, total, halfi);
}

// round 14
// speedup vs baseline: 1.0113x; 1.0113x over previous
#include <cuda_runtime.h>

// FINAL: out[b,i,j,f] = x[b,i,f] * y[b,j,f]; d_out second half = 0.75 * first.
// One thread per (b, i, f4): 4 coalesced float4 loads (x[b,i], y[b,0..2]),
// 6 coalesced float4 stores grouped by output half. 64-thread blocks
// (finest-grain HW work distribution: best measured DRAM eff 83.7%, 6631GB/s,
// ncu dur 176.4us — best of all 9 passing variants).
// Traffic = mandatory 1.17GB; at the chip's mixed 1:3 R/W DRAM ceiling.
// Rejected by measurement: ldcs/stcs, v8 256-bit ld/st, persistent grid,
// batch-2 unrolling, single-linear-stream stores, coarser CTAs.

__global__ __launch_bounds__(64)
void tp_kernel(const float4* __restrict__ x,
               const float4* __restrict__ y,
               float4* __restrict__ out,
               unsigned total, unsigned halfi)
{
    unsigned idx = blockIdx.x * blockDim.x + threadIdx.x;
    if (idx >= total) return;

    unsigned f4 = idx & 31u;
    unsigned g  = idx >> 5;          // b*3 + i
    unsigned b  = g / 3u;
    unsigned i  = g - b * 3u;

    float4 xv = x[g * 32u + f4];

    float4 yv[3];
#pragma unroll
    for (int j = 0; j < 3; j++)
        yv[j] = y[(b * 3u + j) * 32u + f4];

    float4 p[3];
#pragma unroll
    for (int j = 0; j < 3; j++) {
        p[j].x = xv.x * yv[j].x;
        p[j].y = xv.y * yv[j].y;
        p[j].z = xv.z * yv[j].z;
        p[j].w = xv.w * yv[j].w;
    }

    unsigned obase = (b * 9u + i * 3u) * 32u + f4;

#pragma unroll
    for (int j = 0; j < 3; j++)
        out[obase + j * 32u] = p[j];

#pragma unroll
    for (int j = 0; j < 3; j++) {
        float4 q;
        q.x = 0.75f * p[j].x;
        q.y = 0.75f * p[j].y;
        q.z = 0.75f * p[j].z;
        q.w = 0.75f * p[j].w;
        out[halfi + obase + j * 32u] = q;
    }
}

extern "C" void kernel_launch(void* const* d_in, const int* in_sizes, int n_in,
                              void* d_out, int out_size)
{
    const float4* x = (const float4*)d_in[0];
    const float4* y = (const float4*)d_in[1];
    float4* out = (float4*)d_out;

    int B = in_sizes[0] / (3 * 128);          // 100000
    unsigned total = (unsigned)B * 3u * 32u;  // threads: (b, i, f4)
    unsigned halfi = (unsigned)B * 9u * 32u;  // float4 elems in first half
    int threads = 64;
    int blocks = (int)((total + threads - 1) / threads);
    tp_kernel<<<blocks, threads>>>(x, y, out, total, halfi);
}